// round 3
// baseline (speedup 1.0000x reference)
#include <cuda_runtime.h>

// Precomputed cos/sin of weights[0,0]; filled by a 1-thread prelude kernel.
__device__ float2 g_cs;

__global__ void rt_prelude(const float* __restrict__ w) {
    float s, c;
    sincosf(w[0], &s, &c);
    g_cs = make_float2(c, s);
}

// x: (B=256, F=2048, J=25, C=2) fp32, row-major. Row = 50 floats = 200 B.
// Joints 0..7 rotated by R = [[c,-s],[s,c]] (out = x @ R):
//   nx = c*x + s*y ; ny = c*y - s*x
// Joints 8..24 copied through.
// Pairs start at even float offsets; every float4 holds exactly 2 full pairs.
__global__ void __launch_bounds__(256)
rt_rotate(const float4* __restrict__ x, float4* __restrict__ out, int n4) {
    int idx = blockIdx.x * blockDim.x + threadIdx.x;
    if (idx >= n4) return;

    const float2 cs = g_cs;
    const float c = cs.x, s = cs.y;

    float4 v = x[idx];

    // Global pair index of the first (x,y) pair in this float4.
    unsigned p0 = (unsigned)idx * 2u;
    unsigned j0 = p0 % 25u;                    // joint index of pair 0
    unsigned j1 = (j0 + 1u == 25u) ? 0u : j0 + 1u;  // joint index of pair 1

    if (j0 < 8u) {
        float nx = fmaf(c, v.x, s * v.y);
        float ny = fmaf(c, v.y, -s * v.x);
        v.x = nx; v.y = ny;
    }
    if (j1 < 8u) {
        float nx = fmaf(c, v.z, s * v.w);
        float ny = fmaf(c, v.w, -s * v.z);
        v.z = nx; v.w = ny;
    }

    out[idx] = v;
}

extern "C" void kernel_launch(void* const* d_in, const int* in_sizes, int n_in,
                              void* d_out, int out_size) {
    const float* x = (const float*)d_in[0];
    const float* w = (const float*)d_in[1];
    float* out = (float*)d_out;

    // Compute cos/sin of weights[0,0] once.
    rt_prelude<<<1, 1>>>(w);

    int n = in_sizes[0];          // 26,214,400 floats (divisible by 4)
    int n4 = n / 4;               // 6,553,600 float4s
    int threads = 256;
    int blocks = (n4 + threads - 1) / threads;
    rt_rotate<<<blocks, threads>>>((const float4*)x, (float4*)out, n4);
}

// round 4
// speedup vs baseline: 1.0282x; 1.0282x over previous
#include <cuda_runtime.h>

// x: (B=256, F=2048, J=25, C=2) fp32, row-major. Row = 50 floats = 200 B.
// Joints 0..7 rotated by R = [[c,-s],[s,c]] (out = x @ R):
//   nx = c*x + s*y ; ny = c*y - s*x
// Joints 8..24 copied through.
// Pairs start at even float offsets; every float4 holds exactly 2 full pairs.
//
// Single kernel: theta = w[0] is a uniform broadcast load; __sincosf is 2 MUFU
// ops per warp, hidden behind the DRAM-bound stream. Each thread handles TWO
// float4s (coalesced, +blockDim stride) for MLP=2.

__device__ __forceinline__ void rot2(float& px, float& py, float c, float s) {
    float nx = fmaf(c, px, s * py);
    float ny = fmaf(c, py, -s * px);
    px = nx; py = ny;
}

__global__ void __launch_bounds__(256)
rt_rotate(const float4* __restrict__ x, float4* __restrict__ out,
          const float* __restrict__ w, int n4) {
    const int i0 = blockIdx.x * 512 + threadIdx.x;   // first float4
    const int i1 = i0 + 256;                         // second float4

    float s, c;
    __sincosf(__ldg(w), &s, &c);

    const bool b0 = i0 < n4;
    const bool b1 = i1 < n4;

    float4 v0, v1;
    if (b0) v0 = x[i0];
    if (b1) v1 = x[i1];

    // Joint indices. Pair index of v0 = 2*i0; joint = pair % 25.
    unsigned ja = ((unsigned)i0 * 2u) % 25u;
    unsigned jb = ja + 1u;  if (jb == 25u) jb = 0u;
    // v1's first pair index = 2*i0 + 512; 512 % 25 == 12.
    unsigned jc = ja + 12u; if (jc >= 25u) jc -= 25u;
    unsigned jd = jc + 1u;  if (jd == 25u) jd = 0u;

    if (ja < 8u) rot2(v0.x, v0.y, c, s);
    if (jb < 8u) rot2(v0.z, v0.w, c, s);
    if (jc < 8u) rot2(v1.x, v1.y, c, s);
    if (jd < 8u) rot2(v1.z, v1.w, c, s);

    if (b0) out[i0] = v0;
    if (b1) out[i1] = v1;
}

extern "C" void kernel_launch(void* const* d_in, const int* in_sizes, int n_in,
                              void* d_out, int out_size) {
    const float* x = (const float*)d_in[0];
    const float* w = (const float*)d_in[1];
    float* out = (float*)d_out;

    int n = in_sizes[0];          // 26,214,400 floats (divisible by 4)
    int n4 = n / 4;               // 6,553,600 float4s
    int blocks = (n4 + 511) / 512;  // 2 float4s per thread, 256 threads/block
    rt_rotate<<<blocks, 256>>>((const float4*)x, (float4*)out, w, n4);
}